// round 14
// baseline (speedup 1.0000x reference)
#include <cuda_runtime.h>
#include <cuda_bf16.h>
#include <math.h>
#include <stdint.h>

#define Bc 2
#define Lc 2048
#define Sc 2048
#define Dc 1024
#define Hc 16
#define NSc 8
#define NSLOTc 512
#define HDc 64
#define BLc (Bc*Lc)
#define BSc (Bc*Sc)

typedef __nv_bfloat16 bf16;
typedef __nv_bfloat162 bf162;

// ---------------- scratch ----------------
__device__ __align__(16) bf16 g_Wqh[Dc*Dc], g_Wql[Dc*Dc];
__device__ __align__(16) bf16 g_Wkh[Dc*Dc], g_Wkl[Dc*Dc];
__device__ __align__(16) bf16 g_Wvh[Dc*Dc], g_Wvl[Dc*Dc];
__device__ __align__(16) bf16 g_Woh[Dc*Dc], g_Wol[Dc*Dc];
__device__ __align__(16) bf16 g_memh[NSLOTc*Dc], g_meml[NSLOTc*Dc];
__device__ __align__(16) float g_ek[NSLOTc*Dc], g_ev[NSLOTc*Dc];
__device__ __align__(16) float g_ctab[Sc*NSc];
__device__ __align__(16) float g_WpeT[NSc*Dc];
__device__ __align__(16) bf16 g_Kh[(size_t)BSc*Dc], g_Kl[(size_t)BSc*Dc];
__device__ __align__(16) bf16 g_Vh[(size_t)BSc*Dc], g_Vl[(size_t)BSc*Dc];
__device__ __align__(16) bf16 g_xhh[(size_t)BLc*Dc], g_xhl[(size_t)BLc*Dc];
__device__ __align__(16) bf16 g_Qh[(size_t)BLc*Dc], g_Ql[(size_t)BLc*Dc];
__device__ __align__(16) bf16 g_aoh[(size_t)BLc*Dc], g_aol[(size_t)BLc*Dc];

// ---------------- helpers ----------------
__device__ __forceinline__ uint32_t smem_u32(const void* p) {
    return (uint32_t)__cvta_generic_to_shared(p);
}
__device__ __forceinline__ void ldsm_x4(uint32_t* r, uint32_t a) {
    asm volatile("ldmatrix.sync.aligned.m8n8.x4.shared.b16 {%0,%1,%2,%3}, [%4];"
                 : "=r"(r[0]), "=r"(r[1]), "=r"(r[2]), "=r"(r[3]) : "r"(a));
}
__device__ __forceinline__ void ldsm_x4t(uint32_t* r, uint32_t a) {
    asm volatile("ldmatrix.sync.aligned.m8n8.x4.trans.shared.b16 {%0,%1,%2,%3}, [%4];"
                 : "=r"(r[0]), "=r"(r[1]), "=r"(r[2]), "=r"(r[3]) : "r"(a));
}
__device__ __forceinline__ void mma_(float* c, const uint32_t* a, uint32_t b0, uint32_t b1) {
    asm volatile("mma.sync.aligned.m16n8k16.row.col.f32.bf16.bf16.f32 "
                 "{%0,%1,%2,%3},{%4,%5,%6,%7},{%8,%9},{%0,%1,%2,%3};"
                 : "+f"(c[0]), "+f"(c[1]), "+f"(c[2]), "+f"(c[3])
                 : "r"(a[0]), "r"(a[1]), "r"(a[2]), "r"(a[3]), "r"(b0), "r"(b1));
}
__device__ __forceinline__ void mma3(float* c, const uint32_t* ah, const uint32_t* al,
                                     uint32_t bh0, uint32_t bh1, uint32_t bl0, uint32_t bl1) {
    mma_(c, ah, bh0, bh1); mma_(c, ah, bl0, bl1); mma_(c, al, bh0, bh1);
}
__device__ __forceinline__ void cpa16(uint32_t s, const void* g) {
    asm volatile("cp.async.cg.shared.global [%0], [%1], 16;" :: "r"(s), "l"(g));
}
__device__ __forceinline__ void cpa_commit() { asm volatile("cp.async.commit_group;"); }
__device__ __forceinline__ void sst2(bf16* H, bf16* L, size_t o, float x, float y) {
    bf162 h = __floats2bfloat162_rn(x, y);
    bf162 l = __floats2bfloat162_rn(x - __bfloat162float(h.x), y - __bfloat162float(h.y));
    *(bf162*)(H + o) = h; *(bf162*)(L + o) = l;
}
__device__ __forceinline__ void sst1(bf16* H, bf16* L, size_t o, float x) {
    bf16 h = __float2bfloat16_rn(x);
    H[o] = h; L[o] = __float2bfloat16_rn(x - __bfloat162float(h));
}
__device__ __forceinline__ void splitpack(float x, float y, uint32_t& h, uint32_t& l) {
    bf162 hh = __floats2bfloat162_rn(x, y);
    bf162 ll = __floats2bfloat162_rn(x - __bfloat162float(hh.x), y - __bfloat162float(hh.y));
    h = *(uint32_t*)&hh; l = *(uint32_t*)&ll;
}
__device__ __forceinline__ float blockReduceSum(float v, float* red) {
    int tid = threadIdx.x, lane = tid & 31, w = tid >> 5;
#pragma unroll
    for (int o = 16; o; o >>= 1) v += __shfl_xor_sync(0xffffffffu, v, o);
    if (lane == 0) red[w] = v;
    __syncthreads();
    if (tid == 0) {
        float s = 0.f;
#pragma unroll
        for (int i = 0; i < 8; i++) s += red[i];
        red[0] = s;
    }
    __syncthreads();
    float r = red[0];
    __syncthreads();
    return r;
}
#define SWZ16(r, c) ((c) ^ ((r) & 7))

// ---------------- fused prep: weight splits + ctab + WpeT + ln_rows ----------------
__global__ void prep_kernel(const float* __restrict__ Wq, const float* __restrict__ Wk,
                            const float* __restrict__ Wv, const float* __restrict__ Wo,
                            const float* __restrict__ E, const float* __restrict__ lnkg,
                            const float* __restrict__ lnkb, const float* __restrict__ rhos,
                            const float* __restrict__ Wpe) {
    __shared__ float red[8];
    int w = blockIdx.y, bx = blockIdx.x, tid = threadIdx.x;
    if (w < 4) {
        int i = bx * 256 + tid;
        const float* src = (w == 0) ? Wq : (w == 1) ? Wk : (w == 2) ? Wv : Wo;
        bf16* H = (w == 0) ? g_Wqh : (w == 1) ? g_Wkh : (w == 2) ? g_Wvh : g_Woh;
        bf16* L = (w == 0) ? g_Wql : (w == 1) ? g_Wkl : (w == 2) ? g_Wvl : g_Wol;
        float sc = (w == 0) ? 0.18033688011112042f : 1.0f;   // 0.125 * log2(e)
        float2 v = ((const float2*)src)[i];
        sst2(H, L, (size_t)i * 2, v.x * sc, v.y * sc);
        return;
    }
    if (bx < 64) {                       // ctab
        int i = bx * 256 + tid;
        int s = i >> 3, m = i & 7;
        double age = (double)(Sc - 1 - s);
        g_ctab[i] = (float)exp(age * log((double)rhos[m]));
    } else if (bx < 96) {                // WpeT
        int i = (bx - 64) * 256 + tid;
        g_WpeT[(i & 7) * Dc + (i >> 3)] = Wpe[i];
    } else if (bx < 96 + NSLOTc) {       // ln_rows
        int r = bx - 96;
        float4 x = *(const float4*)(E + (size_t)r * Dc + tid * 4);
        float mean = blockReduceSum(x.x + x.y + x.z + x.w, red) * (1.0f / Dc);
        float d0 = x.x - mean, d1 = x.y - mean, d2 = x.z - mean, d3 = x.w - mean;
        float var = blockReduceSum(d0*d0 + d1*d1 + d2*d2 + d3*d3, red) * (1.0f / Dc);
        float rs = rsqrtf(var + 1e-5f);
        float4 g4 = *(const float4*)(lnkg + tid * 4);
        float4 b4 = *(const float4*)(lnkb + tid * 4);
        size_t o = (size_t)r * Dc + tid * 4;
        sst2(g_memh, g_meml, o,     d0*rs*g4.x + b4.x, d1*rs*g4.y + b4.y);
        sst2(g_memh, g_meml, o + 2, d2*rs*g4.z + b4.z, d3*rs*g4.w + b4.w);
    }
}

// gather + gate, pair-vectorized: thread handles d = e*512 + tid*2 (+1).
__global__ void gather_kernel(const int* __restrict__ xidx) {
    __shared__ float c[NSc];
    int bs = blockIdx.x, tid = threadIdx.x;
    int s = bs & (Sc - 1);
    int idx = xidx[bs];
    if (tid < NSc) c[tid] = g_ctab[s * NSc + tid];
    __syncthreads();
    float cc[NSc];
#pragma unroll
    for (int m = 0; m < NSc; m++) cc[m] = c[m];
    const float* ekr = g_ek + (size_t)idx * Dc;
    const float* evr = g_ev + (size_t)idx * Dc;
    size_t ob = (size_t)bs * Dc;
#pragma unroll
    for (int e = 0; e < 2; e++) {
        int d = e * 512 + tid * 2;
        float t0 = 0.f, t1 = 0.f;
#pragma unroll
        for (int m = 0; m < NSc; m++) {
            float2 wp = *(const float2*)(g_WpeT + m * Dc + d);
            t0 += cc[m] * wp.x; t1 += cc[m] * wp.y;
        }
        float g0 = t0 / (1.0f + __expf(-t0));
        float g1 = t1 / (1.0f + __expf(-t1));
        float2 ek2 = *(const float2*)(ekr + d);
        float2 ev2 = *(const float2*)(evr + d);
        sst2(g_Kh, g_Kl, ob + d, ek2.x * g0, ek2.y * g1);
        sst2(g_Vh, g_Vl, ob + d, ev2.x * g0, ev2.y * g1);
    }
}

__global__ void gateq_ln_kernel(const float* __restrict__ xq, const float* __restrict__ Cs,
                                const float* __restrict__ gw, const float* __restrict__ bw) {
    __shared__ float red[8];
    __shared__ float c[NSc];
    int r = blockIdx.x, tid = threadIdx.x;
    if (tid < NSc) c[tid] = Cs[(size_t)r * NSc + tid];
    __syncthreads();
    float cc[NSc];
#pragma unroll
    for (int m = 0; m < NSc; m++) cc[m] = c[m];
    float y[4];
#pragma unroll
    for (int e = 0; e < 4; e++) {
        int d = e * 256 + tid;
        float t = 0.f;
#pragma unroll
        for (int m = 0; m < NSc; m++) t += cc[m] * g_WpeT[m * Dc + d];
        y[e] = xq[(size_t)r * Dc + d] * (t / (1.0f + __expf(-t)));
    }
    float mean = blockReduceSum(y[0] + y[1] + y[2] + y[3], red) * (1.0f / Dc);
#pragma unroll
    for (int e = 0; e < 4; e++) y[e] -= mean;
    float var = blockReduceSum(y[0]*y[0] + y[1]*y[1] + y[2]*y[2] + y[3]*y[3], red) * (1.0f / Dc);
    float rs = rsqrtf(var + 1e-5f);
#pragma unroll
    for (int e = 0; e < 4; e++) {
        int d = e * 256 + tid;
        sst1(g_xhh, g_xhl, (size_t)r * Dc + d, y[e] * rs * gw[d] + bw[d]);
    }
}

// ---------------- split-bf16 mma.sync GEMM core ----------------
template<bool SPLITOUT>
__device__ __forceinline__
void gemm_core(const bf16* __restrict__ Ah, const bf16* __restrict__ Al,
               const bf16* __restrict__ Bh, const bf16* __restrict__ Bl,
               float* __restrict__ C, bf16* __restrict__ Ch, bf16* __restrict__ Cl,
               int N, int K, int row0, int col0, char* smraw) {
    const int RS = 80, TB = 128 * RS;
    int tid = threadIdx.x, lane = tid & 31, warp = tid >> 5;
    int wm = (warp >> 1) * 32, wn = (warp & 1) * 64;
    int r_ld = tid >> 1;
    const bf16* gp[4];
    gp[0] = Ah + (size_t)(row0 + r_ld) * K + (tid & 1) * 16;
    gp[1] = Al + (size_t)(row0 + r_ld) * K + (tid & 1) * 16;
    gp[2] = Bh + (size_t)(col0 + r_ld) * K + (tid & 1) * 16;
    gp[3] = Bl + (size_t)(col0 + r_ld) * K + (tid & 1) * 16;
    uint32_t sb = smem_u32(smraw);
    uint32_t st = (uint32_t)(r_ld * RS + (tid & 1) * 32);
    auto load = [&](int bf, int k0) {
#pragma unroll
        for (int o = 0; o < 4; o++) {
            uint32_t s = sb + (uint32_t)((bf * 4 + o) * TB) + st;
            cpa16(s, gp[o] + k0); cpa16(s + 16, gp[o] + k0 + 8);
        }
        cpa_commit();
    };
    float acc[2][8][4] = {};
    int mrow = lane & 15, mcb = (lane >> 4) * 16;
    const int KC = K / 32;
    load(0, 0);
    for (int kc = 0; kc < KC; kc++) {
        if (kc + 1 < KC) {
            load((kc + 1) & 1, (kc + 1) * 32);
            asm volatile("cp.async.wait_group 1;");
        } else {
            asm volatile("cp.async.wait_group 0;");
        }
        __syncthreads();
        uint32_t bo = sb + (uint32_t)((kc & 1) * 4 * TB);
#pragma unroll
        for (int ks = 0; ks < 2; ks++) {
            uint32_t ah[2][4], al[2][4];
#pragma unroll
            for (int i = 0; i < 2; i++) {
                uint32_t aa = bo + (uint32_t)((wm + i * 16 + mrow) * RS + ks * 32 + mcb);
                ldsm_x4(ah[i], aa); ldsm_x4(al[i], aa + TB);
            }
#pragma unroll
            for (int j2 = 0; j2 < 4; j2++) {
                uint32_t ba = bo + (uint32_t)(2 * TB + (wn + j2 * 16 + mrow) * RS + ks * 32 + mcb);
                uint32_t bh[4], bl[4];
                ldsm_x4(bh, ba); ldsm_x4(bl, ba + TB);
#pragma unroll
                for (int i = 0; i < 2; i++) {
                    mma3(acc[i][2 * j2],     ah[i], al[i], bh[0], bh[2], bl[0], bl[2]);
                    mma3(acc[i][2 * j2 + 1], ah[i], al[i], bh[1], bh[3], bl[1], bl[3]);
                }
            }
        }
        __syncthreads();
    }
    int r = lane >> 2, q = (lane & 3) * 2;
#pragma unroll
    for (int i = 0; i < 2; i++)
#pragma unroll
        for (int j = 0; j < 8; j++) {
            size_t g0 = (size_t)(row0 + wm + i * 16 + r) * N + col0 + wn + j * 8 + q;
            float* a = acc[i][j];
            if (SPLITOUT) {
                sst2(Ch, Cl, g0, a[0], a[1]);
                sst2(Ch, Cl, g0 + (size_t)8 * N, a[2], a[3]);
            } else {
                *(float2*)(C + g0) = make_float2(a[0], a[1]);
                *(float2*)(C + g0 + (size_t)8 * N) = make_float2(a[2], a[3]);
            }
        }
}

template<bool SPLITOUT>
__global__ __launch_bounds__(256)
void gemm_bs(const bf16* __restrict__ Ah, const bf16* __restrict__ Al,
             const bf16* __restrict__ Bh, const bf16* __restrict__ Bl,
             float* __restrict__ C, bf16* __restrict__ Ch, bf16* __restrict__ Cl,
             int M, int N, int K) {
    extern __shared__ char smraw[];
    gemm_core<SPLITOUT>(Ah, Al, Bh, Bl, C, Ch, Cl, N, K,
                        blockIdx.y * 128, blockIdx.x * 128, smraw);
}

// Batched Q-proj (256 blocks) + K-proj (32) + V-proj (32).
__global__ __launch_bounds__(256)
void gemm_qkv() {
    extern __shared__ char smraw[];
    int bid = blockIdx.x;
    if (bid < 256) {
        gemm_core<true>(g_xhh, g_xhl, g_Wqh, g_Wql, nullptr, g_Qh, g_Ql,
                        Dc, Dc, (bid >> 3) * 128, (bid & 7) * 128, smraw);
    } else if (bid < 288) {
        int id = bid - 256;
        gemm_core<false>(g_memh, g_meml, g_Wkh, g_Wkl, g_ek, nullptr, nullptr,
                         Dc, Dc, (id >> 3) * 128, (id & 7) * 128, smraw);
    } else {
        int id = bid - 288;
        gemm_core<false>(g_memh, g_meml, g_Wvh, g_Wvl, g_ev, nullptr, nullptr,
                         Dc, Dc, (id >> 3) * 128, (id & 7) * 128, smraw);
    }
}

// ---------------- flash attention: 3-stage KV pipeline, 1 sync/chunk, persistent Q frags ----------------
// smem = 3 stages x 32KB. Stage layout: Kh | Kl | Vh | Vl (8KB each).
// Q tile is staged through buffer 2 during the prologue, then buffer 2 joins the rotation.
__global__ __launch_bounds__(256, 2)
void attn_kernel() {
    extern __shared__ char smraw[];
    uint32_t sb = smem_u32(smraw);
    const uint32_t STG = 32768, ARR = 8192, QLOFF = 16384;
    int tid = threadIdx.x, lane = tid & 31, warp = tid >> 5;
    int b = blockIdx.y >> 4, h = blockIdx.y & 15;
    int q0 = blockIdx.x * 128;
    size_t qoff = ((size_t)(b * Lc + q0)) * Dc + h * HDc;
    size_t koff = ((size_t)b * Sc) * Dc + h * HDc;
    // Q tile -> stage 2 buffer (Qh at +0, Ql at +16K)   [group 0]
    {
        int r = tid >> 1, cb = (tid & 1) * 4;
        const bf16* q_h = g_Qh + qoff + (size_t)r * Dc;
        const bf16* q_l = g_Ql + qoff + (size_t)r * Dc;
#pragma unroll
        for (int j = 0; j < 4; j++) {
            int c = cb + j;
            uint32_t d = (uint32_t)(r * 128 + SWZ16(r, c) * 16);
            cpa16(sb + 2 * STG + d, q_h + c * 8);
            cpa16(sb + 2 * STG + QLOFF + d, q_l + c * 8);
        }
        cpa_commit();
    }
    int kr = tid >> 2, kcb = (tid & 3) * 2;
    const bf16* gsrc[4] = {g_Kh + koff + (size_t)kr * Dc, g_Kl + koff + (size_t)kr * Dc,
                           g_Vh + koff + (size_t)kr * Dc, g_Vl + koff + (size_t)kr * Dc};
    uint32_t kdst[2];
#pragma unroll
    for (int j = 0; j < 2; j++)
        kdst[j] = (uint32_t)(kr * 128 + SWZ16(kr, kcb + j) * 16);
    auto loadKV = [&](int stage, int sc) {
        size_t go = (size_t)sc * 64 * Dc;
        uint32_t sbase = sb + (uint32_t)stage * STG;
#pragma unroll
        for (int o = 0; o < 4; o++)
#pragma unroll
            for (int j = 0; j < 2; j++)
                cpa16(sbase + (uint32_t)(o * ARR) + kdst[j], gsrc[o] + go + (kcb + j) * 8);
        cpa_commit();
    };
    loadKV(0, 0);                         // group 1
    loadKV(1, 1);                         // group 2
    asm volatile("cp.async.wait_group 2;");   // Q ready; KV0/KV1 may be in flight
    __syncthreads();
    // persistent Q fragments from stage-2 buffer
    int mrow = lane & 15, mc = lane >> 4;
    uint32_t qh[4][4], ql[4][4];
#pragma unroll
    for (int ks = 0; ks < 4; ks++) {
        int r = warp * 16 + mrow;
        uint32_t d = (uint32_t)(r * 128 + SWZ16(r, ks * 2 + mc) * 16);
        ldsm_x4(qh[ks], sb + 2 * STG + d);
        ldsm_x4(ql[ks], sb + 2 * STG + QLOFF + d);
    }
    __syncthreads();   // all warps' Q-frag reads done before stage 2 is reused (chunk 2)

    float Oa[8][4] = {};
    float mr[2] = {-1e30f, -1e30f}, lrr[2] = {0.f, 0.f};
    const int NC = Sc / 64;
    for (int sc = 0; sc < NC; sc++) {
        // stage sc complete; stage sc+1 may remain outstanding
        if (sc + 1 < NC) asm volatile("cp.async.wait_group 1;");
        else             asm volatile("cp.async.wait_group 0;");
        __syncthreads();   // also releases buffer (sc+2)%3 == (sc-1)%3 for prefetch below
        uint32_t stg = sb + (uint32_t)((sc % 3) * STG);
        // S = Q K^T (base-2 units; log2e/8 folded into Wq)
        float Sa[8][4] = {};
#pragma unroll
        for (int ks = 0; ks < 4; ks++)
#pragma unroll
            for (int j2 = 0; j2 < 4; j2++) {
                int r = j2 * 16 + mrow;
                uint32_t d = (uint32_t)(r * 128 + SWZ16(r, ks * 2 + mc) * 16);
                uint32_t bh[4], bl[4];
                ldsm_x4(bh, stg + d);
                ldsm_x4(bl, stg + ARR + d);
                mma3(Sa[2 * j2],     qh[ks], ql[ks], bh[0], bh[2], bl[0], bl[2]);
                mma3(Sa[2 * j2 + 1], qh[ks], ql[ks], bh[1], bh[3], bl[1], bl[3]);
            }
        // online softmax (base 2)
        float mx[2] = {-1e30f, -1e30f};
#pragma unroll
        for (int j = 0; j < 8; j++) {
            mx[0] = fmaxf(mx[0], fmaxf(Sa[j][0], Sa[j][1]));
            mx[1] = fmaxf(mx[1], fmaxf(Sa[j][2], Sa[j][3]));
        }
        float al2[2];
#pragma unroll
        for (int t = 0; t < 2; t++) {
            mx[t] = fmaxf(mx[t], __shfl_xor_sync(0xffffffffu, mx[t], 1));
            mx[t] = fmaxf(mx[t], __shfl_xor_sync(0xffffffffu, mx[t], 2));
            float nm = fmaxf(mr[t], mx[t]);
            al2[t] = exp2f(mr[t] - nm);
            mr[t] = nm;
        }
        float rs[2] = {0.f, 0.f};
#pragma unroll
        for (int j = 0; j < 8; j++) {
            Sa[j][0] = exp2f(Sa[j][0] - mr[0]); Sa[j][1] = exp2f(Sa[j][1] - mr[0]);
            Sa[j][2] = exp2f(Sa[j][2] - mr[1]); Sa[j][3] = exp2f(Sa[j][3] - mr[1]);
            rs[0] += Sa[j][0] + Sa[j][1]; rs[1] += Sa[j][2] + Sa[j][3];
            Oa[j][0] *= al2[0]; Oa[j][1] *= al2[0];
            Oa[j][2] *= al2[1]; Oa[j][3] *= al2[1];
        }
#pragma unroll
        for (int t = 0; t < 2; t++) {
            rs[t] += __shfl_xor_sync(0xffffffffu, rs[t], 1);
            rs[t] += __shfl_xor_sync(0xffffffffu, rs[t], 2);
            lrr[t] = lrr[t] * al2[t] + rs[t];
        }
        // pack P hi+lo (Sa dies here)
        uint32_t php[4][4], plp[4][4];
#pragma unroll
        for (int kk = 0; kk < 4; kk++) {
            splitpack(Sa[2 * kk][0],     Sa[2 * kk][1],     php[kk][0], plp[kk][0]);
            splitpack(Sa[2 * kk][2],     Sa[2 * kk][3],     php[kk][1], plp[kk][1]);
            splitpack(Sa[2 * kk + 1][0], Sa[2 * kk + 1][1], php[kk][2], plp[kk][2]);
            splitpack(Sa[2 * kk + 1][2], Sa[2 * kk + 1][3], php[kk][3], plp[kk][3]);
        }
        // O += Ph*Vh + Ph*Vl + Pl*Vh
#pragma unroll
        for (int kk = 0; kk < 4; kk++)
#pragma unroll
            for (int j2 = 0; j2 < 4; j2++) {
                int r = kk * 16 + mrow;
                uint32_t d = (uint32_t)(r * 128 + SWZ16(r, j2 * 2 + mc) * 16);
                uint32_t vh[4], vl[4];
                ldsm_x4t(vh, stg + 2 * ARR + d);
                ldsm_x4t(vl, stg + 3 * ARR + d);
                mma3(Oa[2 * j2],     php[kk], plp[kk], vh[0], vh[1], vl[0], vl[1]);
                mma3(Oa[2 * j2 + 1], php[kk], plp[kk], vh[2], vh[3], vl[2], vl[3]);
            }
        // prefetch 2 chunks ahead into the buffer freed by the barrier above
        if (sc + 2 < NC) loadKV((sc + 2) % 3, sc + 2);
    }
    float inv0 = 1.f / lrr[0], inv1 = 1.f / lrr[1];
    int r = lane >> 2, q = (lane & 3) * 2;
    size_t o0 = qoff + (size_t)(warp * 16 + r) * Dc;
#pragma unroll
    for (int j = 0; j < 8; j++) {
        sst2(g_aoh, g_aol, o0 + j * 8 + q, Oa[j][0] * inv0, Oa[j][1] * inv0);
        sst2(g_aoh, g_aol, o0 + (size_t)8 * Dc + j * 8 + q, Oa[j][2] * inv1, Oa[j][3] * inv1);
    }
}

// ---------------- launch ----------------
extern "C" void kernel_launch(void* const* d_in, const int* in_sizes, int n_in,
                              void* d_out, int out_size) {
    const float* x_q  = (const float*)d_in[0];
    const int*   xidx = (const int*)d_in[1];
    const float* E    = (const float*)d_in[2];
    const float* rhos = (const float*)d_in[3];
    const float* Cs   = (const float*)d_in[4];
    const float* Wq   = (const float*)d_in[5];
    const float* Wk   = (const float*)d_in[6];
    const float* Wv   = (const float*)d_in[7];
    const float* Wo   = (const float*)d_in[8];
    const float* Wpe  = (const float*)d_in[9];
    const float* lnkg = (const float*)d_in[10];
    const float* lnkb = (const float*)d_in[11];
    const float* lnqg = (const float*)d_in[12];
    const float* lnqb = (const float*)d_in[13];
    float* out = (float*)d_out;

    bf16 *woh, *wol, *aoh, *aol;
    cudaGetSymbolAddress((void**)&woh, g_Woh); cudaGetSymbolAddress((void**)&wol, g_Wol);
    cudaGetSymbolAddress((void**)&aoh, g_aoh); cudaGetSymbolAddress((void**)&aol, g_aol);

    const int gemm_smem = 8 * 128 * 80;   // 81920
    const int attn_smem = 98304;          // 3 x 32KB stages
    cudaFuncSetAttribute(gemm_bs<false>, cudaFuncAttributeMaxDynamicSharedMemorySize, gemm_smem);
    cudaFuncSetAttribute(gemm_qkv,       cudaFuncAttributeMaxDynamicSharedMemorySize, gemm_smem);
    cudaFuncSetAttribute(attn_kernel,    cudaFuncAttributeMaxDynamicSharedMemorySize, attn_smem);

    prep_kernel<<<dim3(2048, 5), 256>>>(Wq, Wk, Wv, Wo, E, lnkg, lnkb, rhos, Wpe);
    gateq_ln_kernel<<<Bc * Lc, 256>>>(x_q, Cs, lnqg, lnqb);
    gemm_qkv<<<320, 256, gemm_smem>>>();
    gather_kernel<<<Bc * Sc, 256>>>(xidx);
    attn_kernel<<<dim3(Lc / 128, Bc * Hc), 256, attn_smem>>>();
    gemm_bs<false><<<dim3(Dc / 128, BLc / 128), 256, gemm_smem>>>(
        aoh, aol, woh, wol, out, nullptr, nullptr, BLc, Dc, Dc);
}

// round 15
// speedup vs baseline: 1.0024x; 1.0024x over previous
#include <cuda_runtime.h>
#include <cuda_bf16.h>
#include <math.h>
#include <stdint.h>

#define Bc 2
#define Lc 2048
#define Sc 2048
#define Dc 1024
#define Hc 16
#define NSc 8
#define NSLOTc 512
#define HDc 64
#define BLc (Bc*Lc)
#define BSc (Bc*Sc)

typedef __nv_bfloat16 bf16;
typedef __nv_bfloat162 bf162;

// ---------------- scratch ----------------
__device__ __align__(16) bf16 g_Wqh[Dc*Dc], g_Wql[Dc*Dc];
__device__ __align__(16) bf16 g_Wkh[Dc*Dc], g_Wkl[Dc*Dc];
__device__ __align__(16) bf16 g_Wvh[Dc*Dc], g_Wvl[Dc*Dc];
__device__ __align__(16) bf16 g_Woh[Dc*Dc], g_Wol[Dc*Dc];
__device__ __align__(16) bf16 g_memh[NSLOTc*Dc], g_meml[NSLOTc*Dc];
__device__ __align__(16) float g_ek[NSLOTc*Dc], g_ev[NSLOTc*Dc];
__device__ __align__(16) float g_ctab[Sc*NSc];
__device__ __align__(16) float g_WpeT[NSc*Dc];
__device__ __align__(16) bf16 g_Kh[(size_t)BSc*Dc], g_Kl[(size_t)BSc*Dc];
__device__ __align__(16) bf16 g_Vh[(size_t)BSc*Dc], g_Vl[(size_t)BSc*Dc];
__device__ __align__(16) bf16 g_xhh[(size_t)BLc*Dc], g_xhl[(size_t)BLc*Dc];
__device__ __align__(16) bf16 g_Qh[(size_t)BLc*Dc], g_Ql[(size_t)BLc*Dc];
__device__ __align__(16) bf16 g_aoh[(size_t)BLc*Dc], g_aol[(size_t)BLc*Dc];

// ---------------- helpers ----------------
__device__ __forceinline__ uint32_t smem_u32(const void* p) {
    return (uint32_t)__cvta_generic_to_shared(p);
}
__device__ __forceinline__ void ldsm_x4(uint32_t* r, uint32_t a) {
    asm volatile("ldmatrix.sync.aligned.m8n8.x4.shared.b16 {%0,%1,%2,%3}, [%4];"
                 : "=r"(r[0]), "=r"(r[1]), "=r"(r[2]), "=r"(r[3]) : "r"(a));
}
__device__ __forceinline__ void ldsm_x4t(uint32_t* r, uint32_t a) {
    asm volatile("ldmatrix.sync.aligned.m8n8.x4.trans.shared.b16 {%0,%1,%2,%3}, [%4];"
                 : "=r"(r[0]), "=r"(r[1]), "=r"(r[2]), "=r"(r[3]) : "r"(a));
}
__device__ __forceinline__ void mma_(float* c, const uint32_t* a, uint32_t b0, uint32_t b1) {
    asm volatile("mma.sync.aligned.m16n8k16.row.col.f32.bf16.bf16.f32 "
                 "{%0,%1,%2,%3},{%4,%5,%6,%7},{%8,%9},{%0,%1,%2,%3};"
                 : "+f"(c[0]), "+f"(c[1]), "+f"(c[2]), "+f"(c[3])
                 : "r"(a[0]), "r"(a[1]), "r"(a[2]), "r"(a[3]), "r"(b0), "r"(b1));
}
__device__ __forceinline__ void mma3(float* c, const uint32_t* ah, const uint32_t* al,
                                     uint32_t bh0, uint32_t bh1, uint32_t bl0, uint32_t bl1) {
    mma_(c, ah, bh0, bh1); mma_(c, ah, bl0, bl1); mma_(c, al, bh0, bh1);
}
__device__ __forceinline__ void cpa16(uint32_t s, const void* g) {
    asm volatile("cp.async.cg.shared.global [%0], [%1], 16;" :: "r"(s), "l"(g));
}
__device__ __forceinline__ void cpa_commit() { asm volatile("cp.async.commit_group;"); }
__device__ __forceinline__ void sst2(bf16* H, bf16* L, size_t o, float x, float y) {
    bf162 h = __floats2bfloat162_rn(x, y);
    bf162 l = __floats2bfloat162_rn(x - __bfloat162float(h.x), y - __bfloat162float(h.y));
    *(bf162*)(H + o) = h; *(bf162*)(L + o) = l;
}
__device__ __forceinline__ void sst1(bf16* H, bf16* L, size_t o, float x) {
    bf16 h = __float2bfloat16_rn(x);
    H[o] = h; L[o] = __float2bfloat16_rn(x - __bfloat162float(h));
}
__device__ __forceinline__ void splitpack(float x, float y, uint32_t& h, uint32_t& l) {
    bf162 hh = __floats2bfloat162_rn(x, y);
    bf162 ll = __floats2bfloat162_rn(x - __bfloat162float(hh.x), y - __bfloat162float(hh.y));
    h = *(uint32_t*)&hh; l = *(uint32_t*)&ll;
}
__device__ __forceinline__ float blockReduceSum(float v, float* red) {
    int tid = threadIdx.x, lane = tid & 31, w = tid >> 5;
#pragma unroll
    for (int o = 16; o; o >>= 1) v += __shfl_xor_sync(0xffffffffu, v, o);
    if (lane == 0) red[w] = v;
    __syncthreads();
    if (tid == 0) {
        float s = 0.f;
#pragma unroll
        for (int i = 0; i < 8; i++) s += red[i];
        red[0] = s;
    }
    __syncthreads();
    float r = red[0];
    __syncthreads();
    return r;
}
#define SWZ16(r, c) ((c) ^ ((r) & 7))

// ---------------- fused prep: weight splits + ctab + WpeT + ln_rows ----------------
__global__ void prep_kernel(const float* __restrict__ Wq, const float* __restrict__ Wk,
                            const float* __restrict__ Wv, const float* __restrict__ Wo,
                            const float* __restrict__ E, const float* __restrict__ lnkg,
                            const float* __restrict__ lnkb, const float* __restrict__ rhos,
                            const float* __restrict__ Wpe) {
    __shared__ float red[8];
    int w = blockIdx.y, bx = blockIdx.x, tid = threadIdx.x;
    if (w < 4) {
        int i = bx * 256 + tid;
        const float* src = (w == 0) ? Wq : (w == 1) ? Wk : (w == 2) ? Wv : Wo;
        bf16* H = (w == 0) ? g_Wqh : (w == 1) ? g_Wkh : (w == 2) ? g_Wvh : g_Woh;
        bf16* L = (w == 0) ? g_Wql : (w == 1) ? g_Wkl : (w == 2) ? g_Wvl : g_Wol;
        float sc = (w == 0) ? 0.18033688011112042f : 1.0f;   // 0.125 * log2(e)
        float2 v = ((const float2*)src)[i];
        sst2(H, L, (size_t)i * 2, v.x * sc, v.y * sc);
        return;
    }
    if (bx < 64) {                       // ctab
        int i = bx * 256 + tid;
        int s = i >> 3, m = i & 7;
        double age = (double)(Sc - 1 - s);
        g_ctab[i] = (float)exp(age * log((double)rhos[m]));
    } else if (bx < 96) {                // WpeT
        int i = (bx - 64) * 256 + tid;
        g_WpeT[(i & 7) * Dc + (i >> 3)] = Wpe[i];
    } else if (bx < 96 + NSLOTc) {       // ln_rows
        int r = bx - 96;
        float4 x = *(const float4*)(E + (size_t)r * Dc + tid * 4);
        float mean = blockReduceSum(x.x + x.y + x.z + x.w, red) * (1.0f / Dc);
        float d0 = x.x - mean, d1 = x.y - mean, d2 = x.z - mean, d3 = x.w - mean;
        float var = blockReduceSum(d0*d0 + d1*d1 + d2*d2 + d3*d3, red) * (1.0f / Dc);
        float rs = rsqrtf(var + 1e-5f);
        float4 g4 = *(const float4*)(lnkg + tid * 4);
        float4 b4 = *(const float4*)(lnkb + tid * 4);
        size_t o = (size_t)r * Dc + tid * 4;
        sst2(g_memh, g_meml, o,     d0*rs*g4.x + b4.x, d1*rs*g4.y + b4.y);
        sst2(g_memh, g_meml, o + 2, d2*rs*g4.z + b4.z, d3*rs*g4.w + b4.w);
    }
}

// gather + gate, pair-vectorized: thread handles d = e*512 + tid*2 (+1).
__global__ void gather_kernel(const int* __restrict__ xidx) {
    __shared__ float c[NSc];
    int bs = blockIdx.x, tid = threadIdx.x;
    int s = bs & (Sc - 1);
    int idx = xidx[bs];
    if (tid < NSc) c[tid] = g_ctab[s * NSc + tid];
    __syncthreads();
    float cc[NSc];
#pragma unroll
    for (int m = 0; m < NSc; m++) cc[m] = c[m];
    const float* ekr = g_ek + (size_t)idx * Dc;
    const float* evr = g_ev + (size_t)idx * Dc;
    size_t ob = (size_t)bs * Dc;
#pragma unroll
    for (int e = 0; e < 2; e++) {
        int d = e * 512 + tid * 2;
        float t0 = 0.f, t1 = 0.f;
#pragma unroll
        for (int m = 0; m < NSc; m++) {
            float2 wp = *(const float2*)(g_WpeT + m * Dc + d);
            t0 += cc[m] * wp.x; t1 += cc[m] * wp.y;
        }
        float g0 = t0 / (1.0f + __expf(-t0));
        float g1 = t1 / (1.0f + __expf(-t1));
        float2 ek2 = *(const float2*)(ekr + d);
        float2 ev2 = *(const float2*)(evr + d);
        sst2(g_Kh, g_Kl, ob + d, ek2.x * g0, ek2.y * g1);
        sst2(g_Vh, g_Vl, ob + d, ev2.x * g0, ev2.y * g1);
    }
}

__global__ void gateq_ln_kernel(const float* __restrict__ xq, const float* __restrict__ Cs,
                                const float* __restrict__ gw, const float* __restrict__ bw) {
    __shared__ float red[8];
    __shared__ float c[NSc];
    int r = blockIdx.x, tid = threadIdx.x;
    if (tid < NSc) c[tid] = Cs[(size_t)r * NSc + tid];
    __syncthreads();
    float cc[NSc];
#pragma unroll
    for (int m = 0; m < NSc; m++) cc[m] = c[m];
    float y[4];
#pragma unroll
    for (int e = 0; e < 4; e++) {
        int d = e * 256 + tid;
        float t = 0.f;
#pragma unroll
        for (int m = 0; m < NSc; m++) t += cc[m] * g_WpeT[m * Dc + d];
        y[e] = xq[(size_t)r * Dc + d] * (t / (1.0f + __expf(-t)));
    }
    float mean = blockReduceSum(y[0] + y[1] + y[2] + y[3], red) * (1.0f / Dc);
#pragma unroll
    for (int e = 0; e < 4; e++) y[e] -= mean;
    float var = blockReduceSum(y[0]*y[0] + y[1]*y[1] + y[2]*y[2] + y[3]*y[3], red) * (1.0f / Dc);
    float rs = rsqrtf(var + 1e-5f);
#pragma unroll
    for (int e = 0; e < 4; e++) {
        int d = e * 256 + tid;
        sst1(g_xhh, g_xhl, (size_t)r * Dc + d, y[e] * rs * gw[d] + bw[d]);
    }
}

// ---------------- split-bf16 mma.sync GEMM core ----------------
template<bool SPLITOUT>
__device__ __forceinline__
void gemm_core(const bf16* __restrict__ Ah, const bf16* __restrict__ Al,
               const bf16* __restrict__ Bh, const bf16* __restrict__ Bl,
               float* __restrict__ C, bf16* __restrict__ Ch, bf16* __restrict__ Cl,
               int N, int K, int row0, int col0, char* smraw) {
    const int RS = 80, TB = 128 * RS;
    int tid = threadIdx.x, lane = tid & 31, warp = tid >> 5;
    int wm = (warp >> 1) * 32, wn = (warp & 1) * 64;
    int r_ld = tid >> 1;
    const bf16* gp[4];
    gp[0] = Ah + (size_t)(row0 + r_ld) * K + (tid & 1) * 16;
    gp[1] = Al + (size_t)(row0 + r_ld) * K + (tid & 1) * 16;
    gp[2] = Bh + (size_t)(col0 + r_ld) * K + (tid & 1) * 16;
    gp[3] = Bl + (size_t)(col0 + r_ld) * K + (tid & 1) * 16;
    uint32_t sb = smem_u32(smraw);
    uint32_t st = (uint32_t)(r_ld * RS + (tid & 1) * 32);
    auto load = [&](int bf, int k0) {
#pragma unroll
        for (int o = 0; o < 4; o++) {
            uint32_t s = sb + (uint32_t)((bf * 4 + o) * TB) + st;
            cpa16(s, gp[o] + k0); cpa16(s + 16, gp[o] + k0 + 8);
        }
        cpa_commit();
    };
    float acc[2][8][4] = {};
    int mrow = lane & 15, mcb = (lane >> 4) * 16;
    const int KC = K / 32;
    load(0, 0);
    for (int kc = 0; kc < KC; kc++) {
        if (kc + 1 < KC) {
            load((kc + 1) & 1, (kc + 1) * 32);
            asm volatile("cp.async.wait_group 1;");
        } else {
            asm volatile("cp.async.wait_group 0;");
        }
        __syncthreads();
        uint32_t bo = sb + (uint32_t)((kc & 1) * 4 * TB);
#pragma unroll
        for (int ks = 0; ks < 2; ks++) {
            uint32_t ah[2][4], al[2][4];
#pragma unroll
            for (int i = 0; i < 2; i++) {
                uint32_t aa = bo + (uint32_t)((wm + i * 16 + mrow) * RS + ks * 32 + mcb);
                ldsm_x4(ah[i], aa); ldsm_x4(al[i], aa + TB);
            }
#pragma unroll
            for (int j2 = 0; j2 < 4; j2++) {
                uint32_t ba = bo + (uint32_t)(2 * TB + (wn + j2 * 16 + mrow) * RS + ks * 32 + mcb);
                uint32_t bh[4], bl[4];
                ldsm_x4(bh, ba); ldsm_x4(bl, ba + TB);
#pragma unroll
                for (int i = 0; i < 2; i++) {
                    mma3(acc[i][2 * j2],     ah[i], al[i], bh[0], bh[2], bl[0], bl[2]);
                    mma3(acc[i][2 * j2 + 1], ah[i], al[i], bh[1], bh[3], bl[1], bl[3]);
                }
            }
        }
        __syncthreads();
    }
    int r = lane >> 2, q = (lane & 3) * 2;
#pragma unroll
    for (int i = 0; i < 2; i++)
#pragma unroll
        for (int j = 0; j < 8; j++) {
            size_t g0 = (size_t)(row0 + wm + i * 16 + r) * N + col0 + wn + j * 8 + q;
            float* a = acc[i][j];
            if (SPLITOUT) {
                sst2(Ch, Cl, g0, a[0], a[1]);
                sst2(Ch, Cl, g0 + (size_t)8 * N, a[2], a[3]);
            } else {
                *(float2*)(C + g0) = make_float2(a[0], a[1]);
                *(float2*)(C + g0 + (size_t)8 * N) = make_float2(a[2], a[3]);
            }
        }
}

template<bool SPLITOUT>
__global__ __launch_bounds__(256)
void gemm_bs(const bf16* __restrict__ Ah, const bf16* __restrict__ Al,
             const bf16* __restrict__ Bh, const bf16* __restrict__ Bl,
             float* __restrict__ C, bf16* __restrict__ Ch, bf16* __restrict__ Cl,
             int M, int N, int K) {
    extern __shared__ char smraw[];
    gemm_core<SPLITOUT>(Ah, Al, Bh, Bl, C, Ch, Cl, N, K,
                        blockIdx.y * 128, blockIdx.x * 128, smraw);
}

// Batched Q-proj (256 blocks) + K-proj (32) + V-proj (32).
__global__ __launch_bounds__(256)
void gemm_qkv() {
    extern __shared__ char smraw[];
    int bid = blockIdx.x;
    if (bid < 256) {
        gemm_core<true>(g_xhh, g_xhl, g_Wqh, g_Wql, nullptr, g_Qh, g_Ql,
                        Dc, Dc, (bid >> 3) * 128, (bid & 7) * 128, smraw);
    } else if (bid < 288) {
        int id = bid - 256;
        gemm_core<false>(g_memh, g_meml, g_Wkh, g_Wkl, g_ek, nullptr, nullptr,
                         Dc, Dc, (id >> 3) * 128, (id & 7) * 128, smraw);
    } else {
        int id = bid - 288;
        gemm_core<false>(g_memh, g_meml, g_Wvh, g_Wvl, g_ev, nullptr, nullptr,
                         Dc, Dc, (id >> 3) * 128, (id & 7) * 128, smraw);
    }
}

// ---------------- flash attention: 3-stage KV pipeline, 1 sync/chunk, persistent Q frags ----------------
// smem = 3 stages x 32KB. Stage layout: Kh | Kl | Vh | Vl (8KB each).
// Q tile is staged through buffer 2 during the prologue, then buffer 2 joins the rotation.
__global__ __launch_bounds__(256, 2)
void attn_kernel() {
    extern __shared__ char smraw[];
    uint32_t sb = smem_u32(smraw);
    const uint32_t STG = 32768, ARR = 8192, QLOFF = 16384;
    int tid = threadIdx.x, lane = tid & 31, warp = tid >> 5;
    int b = blockIdx.y >> 4, h = blockIdx.y & 15;
    int q0 = blockIdx.x * 128;
    size_t qoff = ((size_t)(b * Lc + q0)) * Dc + h * HDc;
    size_t koff = ((size_t)b * Sc) * Dc + h * HDc;
    // Q tile -> stage 2 buffer (Qh at +0, Ql at +16K)   [group 0]
    {
        int r = tid >> 1, cb = (tid & 1) * 4;
        const bf16* q_h = g_Qh + qoff + (size_t)r * Dc;
        const bf16* q_l = g_Ql + qoff + (size_t)r * Dc;
#pragma unroll
        for (int j = 0; j < 4; j++) {
            int c = cb + j;
            uint32_t d = (uint32_t)(r * 128 + SWZ16(r, c) * 16);
            cpa16(sb + 2 * STG + d, q_h + c * 8);
            cpa16(sb + 2 * STG + QLOFF + d, q_l + c * 8);
        }
        cpa_commit();
    }
    int kr = tid >> 2, kcb = (tid & 3) * 2;
    const bf16* gsrc[4] = {g_Kh + koff + (size_t)kr * Dc, g_Kl + koff + (size_t)kr * Dc,
                           g_Vh + koff + (size_t)kr * Dc, g_Vl + koff + (size_t)kr * Dc};
    uint32_t kdst[2];
#pragma unroll
    for (int j = 0; j < 2; j++)
        kdst[j] = (uint32_t)(kr * 128 + SWZ16(kr, kcb + j) * 16);
    auto loadKV = [&](int stage, int sc) {
        size_t go = (size_t)sc * 64 * Dc;
        uint32_t sbase = sb + (uint32_t)stage * STG;
#pragma unroll
        for (int o = 0; o < 4; o++)
#pragma unroll
            for (int j = 0; j < 2; j++)
                cpa16(sbase + (uint32_t)(o * ARR) + kdst[j], gsrc[o] + go + (kcb + j) * 8);
        cpa_commit();
    };
    loadKV(0, 0);                         // group 1
    loadKV(1, 1);                         // group 2
    asm volatile("cp.async.wait_group 2;");   // Q ready; KV0/KV1 may be in flight
    __syncthreads();
    // persistent Q fragments from stage-2 buffer
    int mrow = lane & 15, mc = lane >> 4;
    uint32_t qh[4][4], ql[4][4];
#pragma unroll
    for (int ks = 0; ks < 4; ks++) {
        int r = warp * 16 + mrow;
        uint32_t d = (uint32_t)(r * 128 + SWZ16(r, ks * 2 + mc) * 16);
        ldsm_x4(qh[ks], sb + 2 * STG + d);
        ldsm_x4(ql[ks], sb + 2 * STG + QLOFF + d);
    }
    __syncthreads();   // all warps' Q-frag reads done before stage 2 is reused (chunk 2)

    float Oa[8][4] = {};
    float mr[2] = {-1e30f, -1e30f}, lrr[2] = {0.f, 0.f};
    const int NC = Sc / 64;
    for (int sc = 0; sc < NC; sc++) {
        // stage sc complete; stage sc+1 may remain outstanding
        if (sc + 1 < NC) asm volatile("cp.async.wait_group 1;");
        else             asm volatile("cp.async.wait_group 0;");
        __syncthreads();   // also releases buffer (sc+2)%3 == (sc-1)%3 for prefetch below
        uint32_t stg = sb + (uint32_t)((sc % 3) * STG);
        // S = Q K^T (base-2 units; log2e/8 folded into Wq)
        float Sa[8][4] = {};
#pragma unroll
        for (int ks = 0; ks < 4; ks++)
#pragma unroll
            for (int j2 = 0; j2 < 4; j2++) {
                int r = j2 * 16 + mrow;
                uint32_t d = (uint32_t)(r * 128 + SWZ16(r, ks * 2 + mc) * 16);
                uint32_t bh[4], bl[4];
                ldsm_x4(bh, stg + d);
                ldsm_x4(bl, stg + ARR + d);
                mma3(Sa[2 * j2],     qh[ks], ql[ks], bh[0], bh[2], bl[0], bl[2]);
                mma3(Sa[2 * j2 + 1], qh[ks], ql[ks], bh[1], bh[3], bl[1], bl[3]);
            }
        // online softmax (base 2)
        float mx[2] = {-1e30f, -1e30f};
#pragma unroll
        for (int j = 0; j < 8; j++) {
            mx[0] = fmaxf(mx[0], fmaxf(Sa[j][0], Sa[j][1]));
            mx[1] = fmaxf(mx[1], fmaxf(Sa[j][2], Sa[j][3]));
        }
        float al2[2];
#pragma unroll
        for (int t = 0; t < 2; t++) {
            mx[t] = fmaxf(mx[t], __shfl_xor_sync(0xffffffffu, mx[t], 1));
            mx[t] = fmaxf(mx[t], __shfl_xor_sync(0xffffffffu, mx[t], 2));
            float nm = fmaxf(mr[t], mx[t]);
            al2[t] = exp2f(mr[t] - nm);
            mr[t] = nm;
        }
        float rs[2] = {0.f, 0.f};
#pragma unroll
        for (int j = 0; j < 8; j++) {
            Sa[j][0] = exp2f(Sa[j][0] - mr[0]); Sa[j][1] = exp2f(Sa[j][1] - mr[0]);
            Sa[j][2] = exp2f(Sa[j][2] - mr[1]); Sa[j][3] = exp2f(Sa[j][3] - mr[1]);
            rs[0] += Sa[j][0] + Sa[j][1]; rs[1] += Sa[j][2] + Sa[j][3];
            Oa[j][0] *= al2[0]; Oa[j][1] *= al2[0];
            Oa[j][2] *= al2[1]; Oa[j][3] *= al2[1];
        }
#pragma unroll
        for (int t = 0; t < 2; t++) {
            rs[t] += __shfl_xor_sync(0xffffffffu, rs[t], 1);
            rs[t] += __shfl_xor_sync(0xffffffffu, rs[t], 2);
            lrr[t] = lrr[t] * al2[t] + rs[t];
        }
        // pack P hi+lo (Sa dies here)
        uint32_t php[4][4], plp[4][4];
#pragma unroll
        for (int kk = 0; kk < 4; kk++) {
            splitpack(Sa[2 * kk][0],     Sa[2 * kk][1],     php[kk][0], plp[kk][0]);
            splitpack(Sa[2 * kk][2],     Sa[2 * kk][3],     php[kk][1], plp[kk][1]);
            splitpack(Sa[2 * kk + 1][0], Sa[2 * kk + 1][1], php[kk][2], plp[kk][2]);
            splitpack(Sa[2 * kk + 1][2], Sa[2 * kk + 1][3], php[kk][3], plp[kk][3]);
        }
        // O += Ph*Vh + Ph*Vl + Pl*Vh
#pragma unroll
        for (int kk = 0; kk < 4; kk++)
#pragma unroll
            for (int j2 = 0; j2 < 4; j2++) {
                int r = kk * 16 + mrow;
                uint32_t d = (uint32_t)(r * 128 + SWZ16(r, j2 * 2 + mc) * 16);
                uint32_t vh[4], vl[4];
                ldsm_x4t(vh, stg + 2 * ARR + d);
                ldsm_x4t(vl, stg + 3 * ARR + d);
                mma3(Oa[2 * j2],     php[kk], plp[kk], vh[0], vh[1], vl[0], vl[1]);
                mma3(Oa[2 * j2 + 1], php[kk], plp[kk], vh[2], vh[3], vl[2], vl[3]);
            }
        // prefetch 2 chunks ahead into the buffer freed by the barrier above
        if (sc + 2 < NC) loadKV((sc + 2) % 3, sc + 2);
    }
    float inv0 = 1.f / lrr[0], inv1 = 1.f / lrr[1];
    int r = lane >> 2, q = (lane & 3) * 2;
    size_t o0 = qoff + (size_t)(warp * 16 + r) * Dc;
#pragma unroll
    for (int j = 0; j < 8; j++) {
        sst2(g_aoh, g_aol, o0 + j * 8 + q, Oa[j][0] * inv0, Oa[j][1] * inv0);
        sst2(g_aoh, g_aol, o0 + (size_t)8 * Dc + j * 8 + q, Oa[j][2] * inv1, Oa[j][3] * inv1);
    }
}

// ---------------- launch ----------------
extern "C" void kernel_launch(void* const* d_in, const int* in_sizes, int n_in,
                              void* d_out, int out_size) {
    const float* x_q  = (const float*)d_in[0];
    const int*   xidx = (const int*)d_in[1];
    const float* E    = (const float*)d_in[2];
    const float* rhos = (const float*)d_in[3];
    const float* Cs   = (const float*)d_in[4];
    const float* Wq   = (const float*)d_in[5];
    const float* Wk   = (const float*)d_in[6];
    const float* Wv   = (const float*)d_in[7];
    const float* Wo   = (const float*)d_in[8];
    const float* Wpe  = (const float*)d_in[9];
    const float* lnkg = (const float*)d_in[10];
    const float* lnkb = (const float*)d_in[11];
    const float* lnqg = (const float*)d_in[12];
    const float* lnqb = (const float*)d_in[13];
    float* out = (float*)d_out;

    bf16 *woh, *wol, *aoh, *aol;
    cudaGetSymbolAddress((void**)&woh, g_Woh); cudaGetSymbolAddress((void**)&wol, g_Wol);
    cudaGetSymbolAddress((void**)&aoh, g_aoh); cudaGetSymbolAddress((void**)&aol, g_aol);

    const int gemm_smem = 8 * 128 * 80;   // 81920
    const int attn_smem = 98304;          // 3 x 32KB stages
    cudaFuncSetAttribute(gemm_bs<false>, cudaFuncAttributeMaxDynamicSharedMemorySize, gemm_smem);
    cudaFuncSetAttribute(gemm_qkv,       cudaFuncAttributeMaxDynamicSharedMemorySize, gemm_smem);
    cudaFuncSetAttribute(attn_kernel,    cudaFuncAttributeMaxDynamicSharedMemorySize, attn_smem);

    prep_kernel<<<dim3(2048, 5), 256>>>(Wq, Wk, Wv, Wo, E, lnkg, lnkb, rhos, Wpe);
    gateq_ln_kernel<<<Bc * Lc, 256>>>(x_q, Cs, lnqg, lnqb);
    gemm_qkv<<<320, 256, gemm_smem>>>();
    gather_kernel<<<Bc * Sc, 256>>>(xidx);
    attn_kernel<<<dim3(Lc / 128, Bc * Hc), 256, attn_smem>>>();
    gemm_bs<false><<<dim3(Dc / 128, BLc / 128), 256, gemm_smem>>>(
        aoh, aol, woh, wol, out, nullptr, nullptr, BLc, Dc, Dc);
}